// round 8
// baseline (speedup 1.0000x reference)
#include <cuda_runtime.h>
#include <cuda_bf16.h>
#include <cstdint>

// Diagonal linear recurrence with SiLU pre-activation and self-gating.
//   d = sigmoid(log_d);  h_t = d*(silu(x_t) + h_{t-1}) + b;  out = h^2*sigmoid(h)
//
// R6 vs R5 (121us, DRAM 52%, warp0 serial section + 4 barriers/tile):
//  - Chunk-aggregate scan distributed: warp w scans channel w with a 5-step
//    shfl Kogge-Stone affine scan (multiplier P^(2^k), squared each step).
//    No serialized warp, one fewer barrier (3/tile).
//  - 3-stage cp.async pipeline (prefetch distance 2, dynamic smem 57.6KB,
//    2 blocks/SM) so ~2 tiles of loads are always in flight.
//  - aggr/estart padded to stride 33 -> transposed accesses conflict-free.

__device__ __forceinline__ float tanh_fast(float x) {
    float y;
    asm("tanh.approx.f32 %0, %1;" : "=f"(y) : "f"(x));
    return y;
}

__device__ __forceinline__ float fast_sigmoid(float x) {
    // sigmoid(x) = 0.5*tanh(0.5x) + 0.5  -> single MUFU.TANH + FMA
    return fmaf(0.5f, tanh_fast(0.5f * x), 0.5f);
}

__device__ __forceinline__ void cp_async16(float* smem_dst, const float* gsrc) {
    uint32_t saddr = (uint32_t)__cvta_generic_to_shared(smem_dst);
    asm volatile("cp.async.cg.shared.global [%0], [%1], 16;"
                 :: "r"(saddr), "l"(gsrc) : "memory");
}

constexpr int CH   = 32;            // channels per block (one 128B line)
constexpr int CK   = 32;            // chunk-warps per block
constexpr int LL   = 4;             // timesteps per chunk per tile
constexpr int TILE = CK * LL;       // 128 timesteps per tile
constexpr int NT   = CH * CK;       // 1024 threads
constexpr int NBUF = 3;             // cp.async pipeline depth
constexpr int SCAN_PAD = 33;        // stride for transposed scan arrays

constexpr int DYN_SMEM_FLOATS = NBUF * TILE * CH + 2 * CK * SCAN_PAD;
constexpr int DYN_SMEM_BYTES  = DYN_SMEM_FLOATS * 4;   // 57600 B

__global__ void __launch_bounds__(NT, 2)
e54_smem_kernel(const float* __restrict__ x,
                const float* __restrict__ h0,
                const float* __restrict__ log_d,
                const float* __restrict__ bias,
                float* __restrict__ out,
                float* __restrict__ h_final,   // may be nullptr
                int B, int T, int D)
{
    extern __shared__ float dynsmem[];
    float* buf    = dynsmem;                      // NBUF * 4096
    float* aggr   = dynsmem + NBUF * TILE * CH;   // [chunk][channel] stride 33
    float* estart = aggr + CK * SCAN_PAD;         // [chunk][channel] stride 33

    const int tid = threadIdx.x;
    const int ch  = tid & (CH - 1);         // lane: channel within block
    const int c   = tid >> 5;               // warp id: chunk index

    const int base = blockIdx.x * CH;
    const int b    = base / D;              // 32 | D -> whole block same batch
    const int ch0  = base - b * D;
    const int chg  = ch0 + ch;

    const float dc = fast_sigmoid(log_d[chg]);
    const float bc = bias[chg];
    const float d2 = dc * dc;
    const float P4 = d2 * d2;               // d^LL for this thread's channel

    // Warp c scans channel c: its composition multiplier is P of channel c,
    // held by lane c of this warp (thread channel == lane id).
    const float pscan = __shfl_sync(0xffffffffu, P4, c);

    // Ppow = pscan^lane  (for applying the carry to chunk start states)
    float Ppow = 1.0f;
    {
        float pp = pscan;
        #pragma unroll
        for (int k = 0; k < 5; k++) {
            if ((ch >> k) & 1) Ppow *= pp;
            pp *= pp;
        }
    }

    // Per-warp inter-tile carry for channel c (uniform across the warp).
    float hcar = h0[base + c];

    // Loader role: one float4 per thread per tile, fully coalesced rows.
    const int q = tid & 7;                  // 16B quad within 128B row
    const int r = tid >> 3;                 // timestep row 0..127
    const float* gbase = x + (size_t)b * T * D + (size_t)r * D + ch0 + q * 4;
    const size_t tile_stride = (size_t)TILE * D;

    float* outp = out + (size_t)b * T * D + (size_t)(c * LL) * D + chg;

    const int ntiles = T / TILE;

    // Prologue: load tiles 0 and 1.
    cp_async16(&buf[0 * TILE * CH + r * CH + q * 4], gbase);
    asm volatile("cp.async.commit_group;" ::: "memory");
    cp_async16(&buf[1 * TILE * CH + r * CH + q * 4], gbase + tile_stride);
    asm volatile("cp.async.commit_group;" ::: "memory");

    int pbuf = 2;                          // next buffer slot to fill
    const float* gpref = gbase + 2 * tile_stride;

    for (int j = 0; j < ntiles; j++) {
        // Prefetch tile j+2 (distance-2 pipeline). Always commit a group so
        // "wait_group 2" deterministically covers tile j's group.
        if (j + 2 < ntiles) {
            cp_async16(&buf[pbuf * TILE * CH + r * CH + q * 4], gpref);
            gpref += tile_stride;
            pbuf = (pbuf + 1 == NBUF) ? 0 : pbuf + 1;
        }
        asm volatile("cp.async.commit_group;" ::: "memory");
        asm volatile("cp.async.wait_group 2;" ::: "memory");
        __syncthreads();                   // tile j visible to all

        const int cb = j % NBUF;

        // ---- Phase A: silu + local scan with zero start ----
        float sv[LL];
        {
            const float* bp = &buf[cb * TILE * CH + (c * LL) * CH + ch];
            float u = 0.0f;
            #pragma unroll
            for (int i = 0; i < LL; i++) {
                float xv = bp[i * CH];
                float xa = xv * fast_sigmoid(xv);
                sv[i] = xa;
                u = fmaf(dc, xa + u, bc);
            }
            aggr[c * SCAN_PAD + ch] = u;   // banks (c+ch)%32: conflict-free
        }
        __syncthreads();

        // ---- Distributed scan: warp c scans channel c over 32 chunks ----
        {
            float v = aggr[ch * SCAN_PAD + c];    // lane = chunk index
            float p = pscan;
            #pragma unroll
            for (int o = 1; o < CK; o <<= 1) {
                float tt = __shfl_up_sync(0xffffffffu, v, o);
                v = (ch >= o) ? fmaf(p, tt, v) : v;
                p *= p;                            // p ends as pscan^32
            }
            float vprev = __shfl_up_sync(0xffffffffu, v, 1);
            float e = fmaf(Ppow, hcar, (ch > 0) ? vprev : 0.0f);
            estart[ch * SCAN_PAD + c] = e;
            float vlast = __shfl_sync(0xffffffffu, v, CK - 1);
            hcar = fmaf(p, hcar, vlast);           // carry to next tile
        }
        __syncthreads();

        // ---- Phase B: replay with correct start state, gated store ----
        {
            float h = estart[c * SCAN_PAD + ch];
            #pragma unroll
            for (int i = 0; i < LL; i++) {
                h = fmaf(dc, sv[i] + h, bc);
                float y = h * h * fast_sigmoid(h);
                outp[(size_t)i * D] = y;           // warp = one 128B line
            }
            outp += tile_stride;
        }
        // No barrier here: the buffer reused by the next prefetch was last
        // read in phase A two iterations ago (guarded by that aggr barrier).
    }

    if (h_final && ch == 0)
        h_final[base + c] = hcar;          // warp c's carry = channel c final
}

// ---------- Fallback (R2 scheme) for unexpected shapes ----------
constexpr int FB_U = 64;

__global__ void __launch_bounds__(128, 1)
e54_serial_kernel(const float* __restrict__ x,
                  const float* __restrict__ h0,
                  const float* __restrict__ log_d,
                  const float* __restrict__ bias,
                  float* __restrict__ out,
                  float* __restrict__ h_final,
                  int B, int T, int D)
{
    int idx = blockIdx.x * blockDim.x + threadIdx.x;
    if (idx >= B * D) return;
    int b = idx / D;
    int c = idx - b * D;

    float dc = fast_sigmoid(log_d[c]);
    float bc = bias[c];
    float h  = h0[idx];

    const float* xp = x   + (size_t)b * T * D + c;
    float*       op = out + (size_t)b * T * D + c;

    int t = 0;
    for (; t + FB_U <= T; t += FB_U) {
        float xv[FB_U];
        #pragma unroll
        for (int u = 0; u < FB_U; u++) xv[u] = xp[(size_t)(t + u) * D];
        #pragma unroll
        for (int u = 0; u < FB_U; u++) xv[u] = xv[u] * fast_sigmoid(xv[u]);
        #pragma unroll
        for (int u = 0; u < FB_U; u++) {
            h = fmaf(dc, xv[u] + h, bc);
            float y = h * h * fast_sigmoid(h);
            op[(size_t)(t + u) * D] = y;
        }
    }
    for (; t < T; t++) {
        float xv = xp[(size_t)t * D];
        float xa = xv * fast_sigmoid(xv);
        h = fmaf(dc, xa + h, bc);
        op[(size_t)t * D] = h * h * fast_sigmoid(h);
    }
    if (h_final) h_final[idx] = h;
}

extern "C" void kernel_launch(void* const* d_in, const int* in_sizes, int n_in,
                              void* d_out, int out_size)
{
    const float* x     = (const float*)d_in[0];
    const float* h0    = (const float*)d_in[1];
    const float* log_d = (const float*)d_in[2];
    const float* bias  = (const float*)d_in[3];
    float* out = (float*)d_out;

    int D  = in_sizes[2];
    int BD = in_sizes[1];
    int B  = BD / D;
    int T  = in_sizes[0] / BD;

    long long main_elems = (long long)B * T * D;
    float* h_final = nullptr;
    if ((long long)out_size >= main_elems + BD) {
        h_final = out + main_elems;   // harness concatenates (output, h_final)
    }

    if ((T % TILE) == 0 && (T / TILE) >= NBUF && (D % CH) == 0 && (BD % CH) == 0) {
        static bool attr_set = false;
        if (!attr_set) {
            cudaFuncSetAttribute(e54_smem_kernel,
                                 cudaFuncAttributeMaxDynamicSharedMemorySize,
                                 DYN_SMEM_BYTES);
            attr_set = true;
        }
        int blocks = BD / CH;   // 512
        e54_smem_kernel<<<blocks, NT, DYN_SMEM_BYTES>>>(x, h0, log_d, bias, out,
                                                        h_final, B, T, D);
    } else {
        int threads = 128;
        int blocks  = (BD + threads - 1) / threads;
        e54_serial_kernel<<<blocks, threads>>>(x, h0, log_d, bias, out,
                                               h_final, B, T, D);
    }
}

// round 9
// speedup vs baseline: 1.3830x; 1.3830x over previous
#include <cuda_runtime.h>
#include <cuda_bf16.h>
#include <cstdint>

// Diagonal linear recurrence with SiLU pre-activation and self-gating.
//   d = sigmoid(log_d);  h_t = d*(silu(x_t) + h_{t-1}) + b;  out = h^2*sigmoid(h)
//
// R7 = R5 skeleton (121us: 2-buffer cp.async, static smem, 32ch x 32chunk
// block) with two surgical changes, keeping register pressure at R5's level
// (R6's distributed scan spilled at the 32-reg cap -> L1 55%, 174us):
//  - Warp-0 serial composition replaced by a register-lean distributed scan:
//    warp w scans channel w via 5-step shfl Kogge-Stone; the inter-tile
//    carry is folded into lane 0's input (v0 += P*hcar) so no pscan^lane
//    power table is needed (that was R6's register fat).
//  - R5's redundant 4th barrier dropped (2 barriers already separate phase-A
//    reads of tile j from the j+1 prefetch overwrite). 3 barriers/tile.

__device__ __forceinline__ float tanh_fast(float x) {
    float y;
    asm("tanh.approx.f32 %0, %1;" : "=f"(y) : "f"(x));
    return y;
}

__device__ __forceinline__ float fast_sigmoid(float x) {
    // sigmoid(x) = 0.5*tanh(0.5x) + 0.5  -> single MUFU.TANH + FMA
    return fmaf(0.5f, tanh_fast(0.5f * x), 0.5f);
}

__device__ __forceinline__ void cp_async16(float* smem_dst, const float* gsrc) {
    uint32_t saddr = (uint32_t)__cvta_generic_to_shared(smem_dst);
    asm volatile("cp.async.cg.shared.global [%0], [%1], 16;"
                 :: "r"(saddr), "l"(gsrc) : "memory");
}

constexpr int CH   = 32;            // channels per block (one 128B line)
constexpr int CK   = 32;            // chunk-warps per block
constexpr int LL   = 4;             // timesteps per chunk per tile
constexpr int TILE = CK * LL;       // 128 timesteps per tile
constexpr int NT   = CH * CK;       // 1024 threads
constexpr int PAD  = 33;            // padded stride: transposed reads conflict-free

__global__ void __launch_bounds__(NT, 2)
e54_smem_kernel(const float* __restrict__ x,
                const float* __restrict__ h0,
                const float* __restrict__ log_d,
                const float* __restrict__ bias,
                float* __restrict__ out,
                float* __restrict__ h_final,   // may be nullptr
                int B, int T, int D)
{
    __shared__ float buf[2][TILE * CH];     // 2 x 16KB
    __shared__ float aggr[CK * PAD];        // [chunk][channel], stride 33
    __shared__ float estart[CK * PAD];      // [chunk][channel], stride 33

    const int tid = threadIdx.x;
    const int ch  = tid & (CH - 1);         // lane: channel within block
    const int c   = tid >> 5;               // warp id: chunk index

    const int base = blockIdx.x * CH;
    const int b    = base / D;              // 32 | D -> whole block same batch
    const int ch0  = base - b * D;
    const int chg  = ch0 + ch;

    const float dc = fast_sigmoid(log_d[chg]);
    const float bc = bias[chg];
    const float d2 = dc * dc;
    const float P4 = d2 * d2;               // d^LL (this thread's channel)

    // Warp c scans channel c; its multiplier is channel c's P4 (held by lane c).
    const float pscan = __shfl_sync(0xffffffffu, P4, c);

    // Per-warp inter-tile carry = state of channel c (uniform across warp).
    float hcar = h0[base + c];

    // Loader role: one float4 per thread per tile, fully coalesced 128B rows.
    const int q = tid & 7;                  // 16B quad within row
    const int r = tid >> 3;                 // timestep row 0..127
    const float* xrow = x + (size_t)b * T * D + ch0;

    const int ntiles = T / TILE;

    // Prologue: load tile 0.
    cp_async16(&buf[0][r * CH + q * 4], xrow + (size_t)r * D + q * 4);
    asm volatile("cp.async.commit_group;" ::: "memory");

    for (int j = 0; j < ntiles; j++) {
        const int cur = j & 1;

        // Prefetch tile j+1 into the other buffer (overlaps this tile's math).
        if (j + 1 < ntiles) {
            cp_async16(&buf[cur ^ 1][r * CH + q * 4],
                       xrow + (size_t)((j + 1) * TILE + r) * D + q * 4);
        }
        asm volatile("cp.async.commit_group;" ::: "memory");
        asm volatile("cp.async.wait_group 1;" ::: "memory");  // tile j ready
        __syncthreads();                                      // (B0) visible

        // ---- Phase A: silu + local scan (h=0); silu kept in registers ----
        float sv[LL];
        {
            const float* bp = &buf[cur][(c * LL) * CH + ch];
            float u = 0.0f;
            #pragma unroll
            for (int i = 0; i < LL; i++) {
                float xv = bp[i * CH];
                float xa = xv * fast_sigmoid(xv);
                sv[i] = xa;
                u = fmaf(dc, xa + u, bc);
            }
            aggr[c * PAD + ch] = u;          // chunk aggregate A_c
        }
        __syncthreads();                     // (B1)

        // ---- Distributed scan: warp c scans channel c over 32 chunks ----
        {
            // lane = chunk index k; carry folded into lane 0's input.
            float v = aggr[ch * PAD + c];    // stride-33: conflict-free
            if (ch == 0) v = fmaf(pscan, hcar, v);
            float p = pscan;
            #pragma unroll
            for (int o = 1; o < CK; o <<= 1) {
                float tt = __shfl_up_sync(0xffffffffu, v, o);
                if (ch >= o) v = fmaf(p, tt, v);
                p *= p;
            }
            // v = S_k (inclusive, carry included). Start state of chunk k:
            float vprev = __shfl_up_sync(0xffffffffu, v, 1);
            estart[ch * PAD + c] = (ch == 0) ? hcar : vprev;
            hcar = __shfl_sync(0xffffffffu, v, CK - 1);   // next tile's carry
        }
        __syncthreads();                     // (B2)

        // ---- Phase B: replay with correct start state, gated store ----
        {
            float h = estart[c * PAD + ch];
            float* orow = out + (size_t)b * T * D
                              + (size_t)(j * TILE + c * LL) * D + chg;
            #pragma unroll
            for (int i = 0; i < LL; i++) {
                h = fmaf(dc, sv[i] + h, bc);
                float y = h * h * fast_sigmoid(h);
                orow[(size_t)i * D] = y;     // warp = one 128B line
            }
        }
        // No end barrier: phase-A reads of tile j precede B1 < B2 < the j+1
        // prefetch that overwrites this buffer -> already ordered.
    }

    if (h_final && ch == 0)
        h_final[base + c] = hcar;            // warp c's carry = channel c final
}

// ---------- Fallback (R2 scheme) for unexpected shapes ----------
constexpr int FB_U = 64;

__global__ void __launch_bounds__(128, 1)
e54_serial_kernel(const float* __restrict__ x,
                  const float* __restrict__ h0,
                  const float* __restrict__ log_d,
                  const float* __restrict__ bias,
                  float* __restrict__ out,
                  float* __restrict__ h_final,
                  int B, int T, int D)
{
    int idx = blockIdx.x * blockDim.x + threadIdx.x;
    if (idx >= B * D) return;
    int b = idx / D;
    int c = idx - b * D;

    float dc = fast_sigmoid(log_d[c]);
    float bc = bias[c];
    float h  = h0[idx];

    const float* xp = x   + (size_t)b * T * D + c;
    float*       op = out + (size_t)b * T * D + c;

    int t = 0;
    for (; t + FB_U <= T; t += FB_U) {
        float xv[FB_U];
        #pragma unroll
        for (int u = 0; u < FB_U; u++) xv[u] = xp[(size_t)(t + u) * D];
        #pragma unroll
        for (int u = 0; u < FB_U; u++) xv[u] = xv[u] * fast_sigmoid(xv[u]);
        #pragma unroll
        for (int u = 0; u < FB_U; u++) {
            h = fmaf(dc, xv[u] + h, bc);
            float y = h * h * fast_sigmoid(h);
            op[(size_t)(t + u) * D] = y;
        }
    }
    for (; t < T; t++) {
        float xv = xp[(size_t)t * D];
        float xa = xv * fast_sigmoid(xv);
        h = fmaf(dc, xa + h, bc);
        op[(size_t)t * D] = h * h * fast_sigmoid(h);
    }
    if (h_final) h_final[idx] = h;
}

extern "C" void kernel_launch(void* const* d_in, const int* in_sizes, int n_in,
                              void* d_out, int out_size)
{
    const float* x     = (const float*)d_in[0];
    const float* h0    = (const float*)d_in[1];
    const float* log_d = (const float*)d_in[2];
    const float* bias  = (const float*)d_in[3];
    float* out = (float*)d_out;

    int D  = in_sizes[2];
    int BD = in_sizes[1];
    int B  = BD / D;
    int T  = in_sizes[0] / BD;

    long long main_elems = (long long)B * T * D;
    float* h_final = nullptr;
    if ((long long)out_size >= main_elems + BD) {
        h_final = out + main_elems;   // harness concatenates (output, h_final)
    }

    if ((T % TILE) == 0 && (D % CH) == 0 && (BD % CH) == 0) {
        int blocks = BD / CH;   // 512
        e54_smem_kernel<<<blocks, NT>>>(x, h0, log_d, bias, out, h_final, B, T, D);
    } else {
        int threads = 128;
        int blocks  = (BD + threads - 1) / threads;
        e54_serial_kernel<<<blocks, threads>>>(x, h0, log_d, bias, out,
                                               h_final, B, T, D);
    }
}

// round 10
// speedup vs baseline: 1.5306x; 1.1067x over previous
#include <cuda_runtime.h>
#include <cuda_bf16.h>
#include <cstdint>

// Diagonal linear recurrence with SiLU pre-activation and self-gating.
//   d = sigmoid(log_d);  h_t = d*(silu(x_t) + h_{t-1}) + b;  out = h^2*sigmoid(h)
//
// R8 = R7 (distributed shfl scan) with the register spill removed. R7 hit the
// __launch_bounds__(1024,2) 32-reg cap and spilled (L1 49%). Changes:
//  - silu values written IN-PLACE into the smem tile (phase A overwrites the
//    cells it read; phase B re-reads via LDS) -> sv[4] regs freed across scan.
//  - estart merged into aggr (each scan cell has a unique reader==writer).
//  - prefetch issued after B1: per-thread order + B0 already orders phase-B
//    reads of a buffer before its overwrite -> still only 3 barriers/tile,
//    and wait_group 0 is exact (one cp.async group outstanding at a time).
//  - 32-bit running element offsets instead of per-tile address recompute.

__device__ __forceinline__ float tanh_fast(float x) {
    float y;
    asm("tanh.approx.f32 %0, %1;" : "=f"(y) : "f"(x));
    return y;
}

__device__ __forceinline__ float fast_sigmoid(float x) {
    // sigmoid(x) = 0.5*tanh(0.5x) + 0.5  -> single MUFU.TANH + FMA
    return fmaf(0.5f, tanh_fast(0.5f * x), 0.5f);
}

__device__ __forceinline__ void cp_async16(float* smem_dst, const float* gsrc) {
    uint32_t saddr = (uint32_t)__cvta_generic_to_shared(smem_dst);
    asm volatile("cp.async.cg.shared.global [%0], [%1], 16;"
                 :: "r"(saddr), "l"(gsrc) : "memory");
}

constexpr int CH   = 32;            // channels per block (one 128B line)
constexpr int CK   = 32;            // chunk-warps per block
constexpr int LL   = 4;             // timesteps per chunk per tile
constexpr int TILE = CK * LL;       // 128 timesteps per tile
constexpr int NT   = CH * CK;       // 1024 threads
constexpr int PAD  = 33;            // padded stride: transposed access conflict-free

__global__ void __launch_bounds__(NT, 2)
e54_smem_kernel(const float* __restrict__ x,
                const float* __restrict__ h0,
                const float* __restrict__ log_d,
                const float* __restrict__ bias,
                float* __restrict__ out,
                float* __restrict__ h_final,   // may be nullptr
                int B, int T, int D)
{
    __shared__ float buf[2][TILE * CH];     // 2 x 16KB x-tiles (then silu in-place)
    __shared__ float aggr[CK * PAD];        // chunk aggregates -> start states

    const int tid = threadIdx.x;
    const int ch  = tid & (CH - 1);         // lane: channel within block
    const int c   = tid >> 5;               // warp id: chunk index

    const int base = blockIdx.x * CH;
    const int b    = base / D;              // 32 | D -> whole block same batch
    const int ch0  = base - b * D;
    const int chg  = ch0 + ch;

    const float dc = fast_sigmoid(log_d[chg]);
    const float bc = bias[chg];
    const float d2 = dc * dc;
    const float P4 = d2 * d2;               // d^LL (this thread's channel)

    // Warp c scans channel c; multiplier = channel c's P4 (held by lane c).
    const float pscan = __shfl_sync(0xffffffffu, P4, c);

    // Per-warp inter-tile carry = state of channel c (uniform across warp).
    float hcar = h0[base + c];

    // Loader role: one float4 per thread per tile, fully coalesced 128B rows.
    const int q = tid & 7;                  // 16B quad within row
    const int r = tid >> 3;                 // timestep row 0..127
    const float* xbase = x + (size_t)b * T * D + (size_t)r * D + ch0 + q * 4;
    float* obase = out + (size_t)b * T * D + (size_t)(c * LL) * D + chg;

    const unsigned tstride = (unsigned)(TILE * D);  // elements per tile
    unsigned loff = tstride;                // next tile to prefetch (tile 1)
    unsigned ooff = 0;

    const int sb = c * (LL * CH) + ch;      // this thread's cells in a tile
    const int ntiles = T / TILE;

    // Prologue: load tile 0.
    cp_async16(&buf[0][r * CH + q * 4], xbase);
    asm volatile("cp.async.commit_group;" ::: "memory");

    for (int j = 0; j < ntiles; j++) {
        asm volatile("cp.async.wait_group 0;" ::: "memory");  // tile j landed
        __syncthreads();                                      // (B0)

        float* bq = &buf[j & 1][sb];

        // ---- Phase A: silu + local scan (h=0); silu written back in-place ----
        {
            float u = 0.0f;
            #pragma unroll
            for (int i = 0; i < LL; i++) {
                float xv = bq[i * CH];
                float xa = xv * fast_sigmoid(xv);
                bq[i * CH] = xa;             // in-place: frees regs across scan
                u = fmaf(dc, xa + u, bc);
            }
            aggr[c * PAD + ch] = u;          // chunk aggregate A_c
        }
        __syncthreads();                     // (B1)

        // Prefetch tile j+1. Safe here: B0(j) ordered everyone's phase-B(j-1)
        // reads of this buffer before now (per-thread order + barrier).
        if (j + 1 < ntiles) {
            cp_async16(&buf[(j & 1) ^ 1][r * CH + q * 4], xbase + loff);
            loff += tstride;
            asm volatile("cp.async.commit_group;" ::: "memory");
        }

        // ---- Distributed scan: warp c scans channel c over 32 chunks ----
        {
            float v = aggr[ch * PAD + c];    // lane = chunk index; conflict-free
            if (ch == 0) v = fmaf(pscan, hcar, v);   // fold inter-tile carry
            float p = pscan;
            #pragma unroll
            for (int o = 1; o < CK; o <<= 1) {
                float tt = __shfl_up_sync(0xffffffffu, v, o);
                if (ch >= o) v = fmaf(p, tt, v);
                p *= p;
            }
            float vprev = __shfl_up_sync(0xffffffffu, v, 1);
            aggr[ch * PAD + c] = (ch == 0) ? hcar : vprev;  // start state, same cell
            hcar = __shfl_sync(0xffffffffu, v, CK - 1);     // next tile's carry
        }
        __syncthreads();                     // (B2)

        // ---- Phase B: replay from smem silu with correct start state ----
        {
            float h = aggr[c * PAD + ch];
            float* op = obase + ooff;
            #pragma unroll
            for (int i = 0; i < LL; i++) {
                float xa = bq[i * CH];       // silu(x), staged in phase A
                h = fmaf(dc, xa + h, bc);
                float y = h * h * fast_sigmoid(h);
                op[(size_t)i * D] = y;       // warp = one 128B line
            }
            ooff += tstride;
        }
        // No end barrier: next overwrite of this buffer is the prefetch after
        // B1(j+1), and B0(j+1) already orders these phase-B reads before it.
    }

    if (h_final && ch == 0)
        h_final[base + c] = hcar;            // warp c's carry = channel c final
}

// ---------- Fallback (R2 scheme) for unexpected shapes ----------
constexpr int FB_U = 64;

__global__ void __launch_bounds__(128, 1)
e54_serial_kernel(const float* __restrict__ x,
                  const float* __restrict__ h0,
                  const float* __restrict__ log_d,
                  const float* __restrict__ bias,
                  float* __restrict__ out,
                  float* __restrict__ h_final,
                  int B, int T, int D)
{
    int idx = blockIdx.x * blockDim.x + threadIdx.x;
    if (idx >= B * D) return;
    int b = idx / D;
    int c = idx - b * D;

    float dc = fast_sigmoid(log_d[c]);
    float bc = bias[c];
    float h  = h0[idx];

    const float* xp = x   + (size_t)b * T * D + c;
    float*       op = out + (size_t)b * T * D + c;

    int t = 0;
    for (; t + FB_U <= T; t += FB_U) {
        float xv[FB_U];
        #pragma unroll
        for (int u = 0; u < FB_U; u++) xv[u] = xp[(size_t)(t + u) * D];
        #pragma unroll
        for (int u = 0; u < FB_U; u++) xv[u] = xv[u] * fast_sigmoid(xv[u]);
        #pragma unroll
        for (int u = 0; u < FB_U; u++) {
            h = fmaf(dc, xv[u] + h, bc);
            float y = h * h * fast_sigmoid(h);
            op[(size_t)(t + u) * D] = y;
        }
    }
    for (; t < T; t++) {
        float xv = xp[(size_t)t * D];
        float xa = xv * fast_sigmoid(xv);
        h = fmaf(dc, xa + h, bc);
        op[(size_t)t * D] = h * h * fast_sigmoid(h);
    }
    if (h_final) h_final[idx] = h;
}

extern "C" void kernel_launch(void* const* d_in, const int* in_sizes, int n_in,
                              void* d_out, int out_size)
{
    const float* x     = (const float*)d_in[0];
    const float* h0    = (const float*)d_in[1];
    const float* log_d = (const float*)d_in[2];
    const float* bias  = (const float*)d_in[3];
    float* out = (float*)d_out;

    int D  = in_sizes[2];
    int BD = in_sizes[1];
    int B  = BD / D;
    int T  = in_sizes[0] / BD;

    long long main_elems = (long long)B * T * D;
    float* h_final = nullptr;
    if ((long long)out_size >= main_elems + BD) {
        h_final = out + main_elems;   // harness concatenates (output, h_final)
    }

    if ((T % TILE) == 0 && (D % CH) == 0 && (BD % CH) == 0) {
        int blocks = BD / CH;   // 512
        e54_smem_kernel<<<blocks, NT>>>(x, h0, log_d, bias, out, h_final, B, T, D);
    } else {
        int threads = 128;
        int blocks  = (BD + threads - 1) / threads;
        e54_serial_kernel<<<blocks, threads>>>(x, h0, log_d, bias, out,
                                               h_final, B, T, D);
    }
}